// round 3
// baseline (speedup 1.0000x reference)
#include <cuda_runtime.h>

// ---------------------------------------------------------------------------
// 2-layer LSTM decoder, persistent CTA = 32 batch rows, f32x2 FFMA GEMVs.
// Weights pre-duplicated into (w,w) f32x2 pairs -> no broadcast MOVs in the
// hot loops: 1 LDG.128 = 2 FFMA2 operands.
// ---------------------------------------------------------------------------

#define ULL unsigned long long
#define T_STEPS 20
#define HP 36

__device__ __forceinline__ ULL pack2(float x, float y) {
    ULL r; asm("mov.b64 %0, {%1, %2};" : "=l"(r) : "f"(x), "f"(y)); return r;
}
__device__ __forceinline__ float2 unpack2(ULL v) {
    float2 r; asm("mov.b64 {%0, %1}, %2;" : "=f"(r.x), "=f"(r.y) : "l"(v)); return r;
}
__device__ __forceinline__ ULL fma2(ULL a, ULL b, ULL c) {
    ULL d; asm("fma.rn.f32x2 %0, %1, %2, %3;" : "=l"(d) : "l"(a), "l"(b), "l"(c)); return d;
}
__device__ __forceinline__ float sigf(float x)  { return __fdividef(1.f, 1.f + __expf(-x)); }
__device__ __forceinline__ float tanhe(float x) { return __fdividef(2.f, 1.f + __expf(-2.f * x)) - 1.f; }

// Duplicated-pair weight storage: a = (i,i | f,f), b = (g,g | o,o) per (k,u).
__device__ ulonglong2 g_u1a[256 * 256 + 256];
__device__ ulonglong2 g_u1b[256 * 256 + 256];
__device__ ulonglong2 g_w2a[256 * 256 + 256];
__device__ ulonglong2 g_w2b[256 * 256 + 256];
__device__ ulonglong2 g_u2a[256 * 256 + 256];
__device__ ulonglong2 g_u2b[256 * 256 + 256];
__device__ ULL        g_pw [256 * 160];        // proj weights (w,w)
__device__ float4     g_w1q[64 * 256];         // W1 gate quads for xw1
__device__ float4     g_xw1q[8192 * 256];      // xw1 quads [row][u]

__global__ void repack_kernel(const float* __restrict__ W1, const float* __restrict__ U1,
                              const float* __restrict__ W2, const float* __restrict__ U2,
                              const float* __restrict__ Wmu, const float* __restrict__ Wlv) {
    int i = blockIdx.x * blockDim.x + threadIdx.x;   // 0..65535
    int k = i >> 8, u = i & 255;
    const float* r;
    if (i < 64 * 256) {
        r = W1 + k * 1024;
        g_w1q[i] = make_float4(r[u], r[256 + u], r[512 + u], r[768 + u]);
    }
    float a, b;
    r = U1 + k * 1024;
    a = r[u]; b = r[256 + u];       g_u1a[i] = make_ulonglong2(pack2(a, a), pack2(b, b));
    a = r[512 + u]; b = r[768 + u]; g_u1b[i] = make_ulonglong2(pack2(a, a), pack2(b, b));
    r = W2 + k * 1024;
    a = r[u]; b = r[256 + u];       g_w2a[i] = make_ulonglong2(pack2(a, a), pack2(b, b));
    a = r[512 + u]; b = r[768 + u]; g_w2b[i] = make_ulonglong2(pack2(a, a), pack2(b, b));
    r = U2 + k * 1024;
    a = r[u]; b = r[256 + u];       g_u2a[i] = make_ulonglong2(pack2(a, a), pack2(b, b));
    a = r[512 + u]; b = r[768 + u]; g_u2b[i] = make_ulonglong2(pack2(a, a), pack2(b, b));
    if (u < 160) {
        float w = (u < 80) ? Wmu[k * 80 + u] : Wlv[k * 80 + (u - 80)];
        g_pw[k * 160 + u] = pack2(w, w);
    }
}

__global__ void xw1_kernel(const float* __restrict__ z1, const float* __restrict__ z2,
                           const float* __restrict__ b1) {
    __shared__ float zt[8][64];
    const int tid = threadIdx.x;
    const int rb  = blockIdx.x * 8;
    for (int i = tid; i < 512; i += 256) {
        int r = i >> 6, k = i & 63;
        zt[r][k] = (k < 32) ? z1[(rb + r) * 32 + k] : z2[(rb + r) * 32 + (k - 32)];
    }
    __syncthreads();
    const int u = tid;
    float4 acc[8];
    #pragma unroll
    for (int r = 0; r < 8; r++) acc[r] = make_float4(0.f, 0.f, 0.f, 0.f);
    for (int k = 0; k < 64; k++) {
        float4 w = g_w1q[k * 256 + u];
        #pragma unroll
        for (int r = 0; r < 8; r++) {
            float zv = zt[r][k];
            acc[r].x += zv * w.x; acc[r].y += zv * w.y;
            acc[r].z += zv * w.z; acc[r].w += zv * w.w;
        }
    }
    float4 bq = make_float4(b1[u], b1[256 + u], b1[512 + u], b1[768 + u]);
    #pragma unroll
    for (int r = 0; r < 8; r++)
        g_xw1q[(size_t)(rb + r) * 256 + u] =
            make_float4(acc[r].x + bq.x, acc[r].y + bq.y, acc[r].z + bq.z, acc[r].w + bq.w);
}

#define SMEM_FLOATS (4 * 256 * HP + 160 * HP)
#define SMEM_BYTES  (SMEM_FLOATS * 4)

__global__ void __launch_bounds__(512, 1) lstm_kernel(
    const float* __restrict__ b2, const float* __restrict__ bmu, const float* __restrict__ blv,
    const float* __restrict__ eps, float* __restrict__ out)
{
    extern __shared__ float sm[];
    float* h1s = sm;
    float* h2s = sm + 256 * HP;
    float* c1s = sm + 2 * 256 * HP;
    float* c2s = sm + 3 * 256 * HP;
    float* prj = sm + 4 * 256 * HP;

    const int tid = threadIdx.x;
    const int u   = tid & 255;
    const int rg  = tid >> 8;
    const int r0  = rg * 16;
    const int rb  = blockIdx.x * 32;

    for (int i = tid; i < 4 * 256 * HP; i += 512) sm[i] = 0.f;
    __syncthreads();

    const float4 b2q = make_float4(b2[u], b2[256 + u], b2[512 + u], b2[768 + u]);

    const bool  pact = tid < 480;
    const int   pcol = tid % 160;
    const int   prg  = tid / 160;
    const int   pr0  = prg * 12;
    const int   pnp  = (prg == 2) ? 4 : 6;
    const float pbias = pact ? ((pcol < 80) ? bmu[pcol] : blv[pcol - 80]) : 0.f;

    const float4* xq = g_xw1q + (size_t)(rb + r0) * 256 + u;

    ULL acc[4][8];

    for (int t = 0; t < T_STEPS; t++) {
        // ================= layer 1: acc = xw1 + h1 @ U1 =================
        #pragma unroll
        for (int p = 0; p < 8; p++) {
            float4 q0 = xq[(2 * p) * 256];
            float4 q1 = xq[(2 * p + 1) * 256];
            acc[0][p] = pack2(q0.x, q1.x);
            acc[1][p] = pack2(q0.y, q1.y);
            acc[2][p] = pack2(q0.z, q1.z);
            acc[3][p] = pack2(q0.w, q1.w);
        }
        {
            ulonglong2 wa = g_u1a[u], wb = g_u1b[u];
            const char* hb = (const char*)(h1s + r0);
            #pragma unroll 2
            for (int k = 0; k < 256; k++) {
                ulonglong2 wan = g_u1a[(k + 1) * 256 + u];
                ulonglong2 wbn = g_u1b[(k + 1) * 256 + u];
                const ulonglong2* hp = (const ulonglong2*)(hb + (size_t)k * (HP * 4));
                ulonglong2 a0 = hp[0], a1 = hp[1];
                #pragma unroll
                for (int p = 0; p < 4; p++) {
                    ULL hv = (p == 0) ? a0.x : (p == 1) ? a0.y : (p == 2) ? a1.x : a1.y;
                    acc[0][p] = fma2(hv, wa.x, acc[0][p]);
                    acc[1][p] = fma2(hv, wa.y, acc[1][p]);
                    acc[2][p] = fma2(hv, wb.x, acc[2][p]);
                    acc[3][p] = fma2(hv, wb.y, acc[3][p]);
                }
                ulonglong2 a2 = hp[2], a3 = hp[3];
                #pragma unroll
                for (int p = 4; p < 8; p++) {
                    ULL hv = (p == 4) ? a2.x : (p == 5) ? a2.y : (p == 6) ? a3.x : a3.y;
                    acc[0][p] = fma2(hv, wa.x, acc[0][p]);
                    acc[1][p] = fma2(hv, wa.y, acc[1][p]);
                    acc[2][p] = fma2(hv, wb.x, acc[2][p]);
                    acc[3][p] = fma2(hv, wb.y, acc[3][p]);
                }
                wa = wan; wb = wbn;
            }
        }
        __syncthreads();
        #pragma unroll
        for (int p = 0; p < 8; p++) {
            float2 iv = unpack2(acc[0][p]);
            float2 fv = unpack2(acc[1][p]);
            float2 gv = unpack2(acc[2][p]);
            float2 ov = unpack2(acc[3][p]);
            int rr = r0 + 2 * p;
            float c0 = c1s[u * HP + rr], c1 = c1s[u * HP + rr + 1];
            c0 = sigf(fv.x) * c0 + sigf(iv.x) * tanhe(gv.x);
            c1 = sigf(fv.y) * c1 + sigf(iv.y) * tanhe(gv.y);
            c1s[u * HP + rr]     = c0;
            c1s[u * HP + rr + 1] = c1;
            *(float2*)(h1s + u * HP + rr) =
                make_float2(sigf(ov.x) * tanhe(c0), sigf(ov.y) * tanhe(c1));
        }
        __syncthreads();

        // ======== layer 2: acc = b2 + h1_new @ W2 + h2 @ U2 ========
        #pragma unroll
        for (int p = 0; p < 8; p++) {
            acc[0][p] = pack2(b2q.x, b2q.x);
            acc[1][p] = pack2(b2q.y, b2q.y);
            acc[2][p] = pack2(b2q.z, b2q.z);
            acc[3][p] = pack2(b2q.w, b2q.w);
        }
        {
            ulonglong2 wa = g_w2a[u], wb = g_w2b[u];
            ulonglong2 va = g_u2a[u], vb = g_u2b[u];
            const char* hb1 = (const char*)(h1s + r0);
            const char* hb2 = (const char*)(h2s + r0);
            #pragma unroll 2
            for (int k = 0; k < 256; k++) {
                ulonglong2 wan = g_w2a[(k + 1) * 256 + u];
                ulonglong2 wbn = g_w2b[(k + 1) * 256 + u];
                ulonglong2 van = g_u2a[(k + 1) * 256 + u];
                ulonglong2 vbn = g_u2b[(k + 1) * 256 + u];
                const ulonglong2* hp1 = (const ulonglong2*)(hb1 + (size_t)k * (HP * 4));
                const ulonglong2* hp2 = (const ulonglong2*)(hb2 + (size_t)k * (HP * 4));
                {
                    ulonglong2 a0 = hp1[0], a1 = hp1[1];
                    ulonglong2 b0 = hp2[0], b1v = hp2[1];
                    #pragma unroll
                    for (int p = 0; p < 4; p++) {
                        ULL h1v = (p == 0) ? a0.x : (p == 1) ? a0.y : (p == 2) ? a1.x : a1.y;
                        ULL h2v = (p == 0) ? b0.x : (p == 1) ? b0.y : (p == 2) ? b1v.x : b1v.y;
                        acc[0][p] = fma2(h1v, wa.x, acc[0][p]);
                        acc[1][p] = fma2(h1v, wa.y, acc[1][p]);
                        acc[2][p] = fma2(h1v, wb.x, acc[2][p]);
                        acc[3][p] = fma2(h1v, wb.y, acc[3][p]);
                        acc[0][p] = fma2(h2v, va.x, acc[0][p]);
                        acc[1][p] = fma2(h2v, va.y, acc[1][p]);
                        acc[2][p] = fma2(h2v, vb.x, acc[2][p]);
                        acc[3][p] = fma2(h2v, vb.y, acc[3][p]);
                    }
                }
                {
                    ulonglong2 a2 = hp1[2], a3 = hp1[3];
                    ulonglong2 b2v = hp2[2], b3 = hp2[3];
                    #pragma unroll
                    for (int p = 4; p < 8; p++) {
                        ULL h1v = (p == 4) ? a2.x : (p == 5) ? a2.y : (p == 6) ? a3.x : a3.y;
                        ULL h2v = (p == 4) ? b2v.x : (p == 5) ? b2v.y : (p == 6) ? b3.x : b3.y;
                        acc[0][p] = fma2(h1v, wa.x, acc[0][p]);
                        acc[1][p] = fma2(h1v, wa.y, acc[1][p]);
                        acc[2][p] = fma2(h1v, wb.x, acc[2][p]);
                        acc[3][p] = fma2(h1v, wb.y, acc[3][p]);
                        acc[0][p] = fma2(h2v, va.x, acc[0][p]);
                        acc[1][p] = fma2(h2v, va.y, acc[1][p]);
                        acc[2][p] = fma2(h2v, vb.x, acc[2][p]);
                        acc[3][p] = fma2(h2v, vb.y, acc[3][p]);
                    }
                }
                wa = wan; wb = wbn; va = van; vb = vbn;
            }
        }
        __syncthreads();
        #pragma unroll
        for (int p = 0; p < 8; p++) {
            float2 iv = unpack2(acc[0][p]);
            float2 fv = unpack2(acc[1][p]);
            float2 gv = unpack2(acc[2][p]);
            float2 ov = unpack2(acc[3][p]);
            int rr = r0 + 2 * p;
            float c0 = c2s[u * HP + rr], c1 = c2s[u * HP + rr + 1];
            c0 = sigf(fv.x) * c0 + sigf(iv.x) * tanhe(gv.x);
            c1 = sigf(fv.y) * c1 + sigf(iv.y) * tanhe(gv.y);
            c2s[u * HP + rr]     = c0;
            c2s[u * HP + rr + 1] = c1;
            float2 hn = make_float2(sigf(ov.x) * tanhe(c0), sigf(ov.y) * tanhe(c1));
            *(float2*)(h2s + u * HP + rr) = hn;
            out[((size_t)(rb + rr) * T_STEPS + t) * 256 + u]     = hn.x;
            out[((size_t)(rb + rr + 1) * T_STEPS + t) * 256 + u] = hn.y;
        }
        __syncthreads();

        // ---- mu / logvar projection ----
        if (pact) {
            ULL pacc[6];
            #pragma unroll
            for (int q = 0; q < 6; q++) pacc[q] = 0ULL;
            const char* hb = (const char*)(h2s + pr0);
            #pragma unroll 2
            for (int k = 0; k < 256; k++) {
                ULL w2 = g_pw[k * 160 + pcol];
                const ULL* hp = (const ULL*)(hb + (size_t)k * (HP * 4));
                #pragma unroll
                for (int q = 0; q < 6; q++)
                    if (q < pnp) pacc[q] = fma2(hp[q], w2, pacc[q]);
            }
            #pragma unroll
            for (int q = 0; q < 6; q++) {
                if (q < pnp) {
                    float2 v = unpack2(pacc[q]);
                    prj[pcol * HP + pr0 + 2 * q]     = v.x + pbias;
                    prj[pcol * HP + pr0 + 2 * q + 1] = v.y + pbias;
                }
            }
        }
        __syncthreads();

        // ---- sample = eps * exp(0.5*mu) + logvar ----
        #pragma unroll
        for (int j = 0; j < 5; j++) {
            int i = tid + j * 512;
            int r = i / 80, f = i - r * 80;
            float mu = prj[f * HP + r];
            float lv = prj[(80 + f) * HP + r];
            size_t base = ((size_t)(rb + r) * T_STEPS + t) * 80 + f;
            float e = eps[base];
            out[41943040u + base] = mu;
            out[55050240u + base] = lv;
            out[68157440u + base] = e * __expf(0.5f * mu) + lv;
        }
    }
}

extern "C" void kernel_launch(void* const* d_in, const int* in_sizes, int n_in,
                              void* d_out, int out_size) {
    // order: x, z1, z2, eps, W1, U1, b1, W2, U2, b2, Wmu, bmu, Wlv, blv
    const float* z1  = (const float*)d_in[1];
    const float* z2  = (const float*)d_in[2];
    const float* eps = (const float*)d_in[3];
    const float* W1  = (const float*)d_in[4];
    const float* U1  = (const float*)d_in[5];
    const float* b1  = (const float*)d_in[6];
    const float* W2  = (const float*)d_in[7];
    const float* U2  = (const float*)d_in[8];
    const float* b2  = (const float*)d_in[9];
    const float* Wmu = (const float*)d_in[10];
    const float* bmu = (const float*)d_in[11];
    const float* Wlv = (const float*)d_in[12];
    const float* blv = (const float*)d_in[13];
    float* out = (float*)d_out;

    cudaFuncSetAttribute(lstm_kernel, cudaFuncAttributeMaxDynamicSharedMemorySize, SMEM_BYTES);

    repack_kernel<<<256, 256>>>(W1, U1, W2, U2, Wmu, Wlv);
    xw1_kernel<<<1024, 256>>>(z1, z2, b1);
    lstm_kernel<<<256, 512, SMEM_BYTES>>>(b2, bmu, blv, eps, out);
}

// round 4
// speedup vs baseline: 1.2593x; 1.2593x over previous
#include <cuda_runtime.h>

// ---------------------------------------------------------------------------
// 2-layer LSTM decoder, persistent CTA = 32 batch rows, f32x2 FFMA GEMVs.
// Round-2 layout (compact float4 gate-quad weights) + fixes:
//   layer2 unroll 2, conflict-free c stride (33), fused proj+sampler,
//   4 barriers per timestep.
// ---------------------------------------------------------------------------

#define ULL unsigned long long
#define T_STEPS 20
#define HP 36   // h row stride (floats): 144B, 16B-aligned for LDS.128 (broadcast reads)
#define CP 33   // c row stride: 33u mod 32 = u -> conflict-free per-thread access

__device__ __forceinline__ ULL pack2(float x, float y) {
    ULL r; asm("mov.b64 %0, {%1, %2};" : "=l"(r) : "f"(x), "f"(y)); return r;
}
__device__ __forceinline__ float2 unpack2(ULL v) {
    float2 r; asm("mov.b64 {%0, %1}, %2;" : "=f"(r.x), "=f"(r.y) : "l"(v)); return r;
}
__device__ __forceinline__ ULL fma2(ULL a, ULL b, ULL c) {
    ULL d; asm("fma.rn.f32x2 %0, %1, %2, %3;" : "=l"(d) : "l"(a), "l"(b), "l"(c)); return d;
}
__device__ __forceinline__ float sigf(float x)  { return __fdividef(1.f, 1.f + __expf(-x)); }
__device__ __forceinline__ float tanhe(float x) { return __fdividef(2.f, 1.f + __expf(-2.f * x)) - 1.f; }

__device__ float4 g_w1q [64  * 256];          // W1 gate quads  [k][u] = (i,f,g,o)
__device__ float4 g_u1q [256 * 256 + 256];    // U1 quads (+pad for prefetch)
__device__ float4 g_w2q [256 * 256 + 256];    // W2 quads
__device__ float4 g_u2q [256 * 256 + 256];    // U2 quads
__device__ float2 g_pw2 [256 * 80 + 80];      // (Wmu, Wlv) pairs [k][f]
__device__ float4 g_xw1q[8192 * 256];         // xw1 quads [row][u], bias folded in

__global__ void repack_kernel(const float* __restrict__ W1, const float* __restrict__ U1,
                              const float* __restrict__ W2, const float* __restrict__ U2,
                              const float* __restrict__ Wmu, const float* __restrict__ Wlv) {
    int i = blockIdx.x * blockDim.x + threadIdx.x;   // 0..65535
    int k = i >> 8, u = i & 255;
    const float* r;
    if (i < 64 * 256) {
        r = W1 + k * 1024;
        g_w1q[i] = make_float4(r[u], r[256 + u], r[512 + u], r[768 + u]);
    }
    r = U1 + k * 1024; g_u1q[i] = make_float4(r[u], r[256 + u], r[512 + u], r[768 + u]);
    r = W2 + k * 1024; g_w2q[i] = make_float4(r[u], r[256 + u], r[512 + u], r[768 + u]);
    r = U2 + k * 1024; g_u2q[i] = make_float4(r[u], r[256 + u], r[512 + u], r[768 + u]);
    if (u < 80) g_pw2[k * 80 + u] = make_float2(Wmu[k * 80 + u], Wlv[k * 80 + u]);
}

__global__ void xw1_kernel(const float* __restrict__ z1, const float* __restrict__ z2,
                           const float* __restrict__ b1) {
    __shared__ float zt[8][64];
    const int tid = threadIdx.x;
    const int rb  = blockIdx.x * 8;
    for (int i = tid; i < 512; i += 256) {
        int r = i >> 6, k = i & 63;
        zt[r][k] = (k < 32) ? z1[(rb + r) * 32 + k] : z2[(rb + r) * 32 + (k - 32)];
    }
    __syncthreads();
    const int u = tid;
    float4 acc[8];
    #pragma unroll
    for (int r = 0; r < 8; r++) acc[r] = make_float4(0.f, 0.f, 0.f, 0.f);
    for (int k = 0; k < 64; k++) {
        float4 w = g_w1q[k * 256 + u];
        #pragma unroll
        for (int r = 0; r < 8; r++) {
            float zv = zt[r][k];
            acc[r].x += zv * w.x; acc[r].y += zv * w.y;
            acc[r].z += zv * w.z; acc[r].w += zv * w.w;
        }
    }
    float4 bq = make_float4(b1[u], b1[256 + u], b1[512 + u], b1[768 + u]);
    #pragma unroll
    for (int r = 0; r < 8; r++)
        g_xw1q[(size_t)(rb + r) * 256 + u] =
            make_float4(acc[r].x + bq.x, acc[r].y + bq.y, acc[r].z + bq.z, acc[r].w + bq.w);
}

// SMEM: h1s/h2s [256][HP], c1s/c2s [256][CP]
#define SMEM_FLOATS (2 * 256 * HP + 2 * 256 * CP)
#define SMEM_BYTES  (SMEM_FLOATS * 4)

__global__ void __launch_bounds__(512, 1) lstm_kernel(
    const float* __restrict__ b2, const float* __restrict__ bmu, const float* __restrict__ blv,
    const float* __restrict__ eps, float* __restrict__ out)
{
    extern __shared__ float sm[];
    float* h1s = sm;
    float* h2s = sm + 256 * HP;
    float* c1s = sm + 2 * 256 * HP;
    float* c2s = c1s + 256 * CP;

    const int tid = threadIdx.x;
    const int u   = tid & 255;
    const int rg  = tid >> 8;
    const int r0  = rg * 16;
    const int rb  = blockIdx.x * 32;

    for (int i = tid; i < SMEM_FLOATS; i += 512) sm[i] = 0.f;
    __syncthreads();

    // bias pairs prebuilt once
    const ULL b2i = pack2(b2[u], b2[u]);
    const ULL b2f = pack2(b2[256 + u], b2[256 + u]);
    const ULL b2g = pack2(b2[512 + u], b2[512 + u]);
    const ULL b2o = pack2(b2[768 + u], b2[768 + u]);

    // fused proj+sampler mapping: 320 threads = 80 features x 4 row groups of 8
    const bool  pact = tid < 320;
    const int   pf   = pact ? (tid % 80) : 0;
    const int   pgp  = pact ? (tid / 80) : 0;     // 0..3
    const int   pr0  = pgp * 8;                   // 4 row pairs
    const float pbmu = pact ? bmu[pf] : 0.f;
    const float pblv = pact ? blv[pf] : 0.f;

    const float4* xq = g_xw1q + (size_t)(rb + r0) * 256 + u;

    ULL acc[4][8];

    for (int t = 0; t < T_STEPS; t++) {
        // ================= layer 1: acc = xw1 + h1 @ U1 =================
        #pragma unroll
        for (int p = 0; p < 8; p++) {
            float4 q0 = xq[(2 * p) * 256];
            float4 q1 = xq[(2 * p + 1) * 256];
            acc[0][p] = pack2(q0.x, q1.x);
            acc[1][p] = pack2(q0.y, q1.y);
            acc[2][p] = pack2(q0.z, q1.z);
            acc[3][p] = pack2(q0.w, q1.w);
        }
        {
            float4 w = g_u1q[u];
            const char* hb = (const char*)(h1s + r0);
            #pragma unroll 2
            for (int k = 0; k < 256; k++) {
                float4 wn = g_u1q[(k + 1) * 256 + u];
                ULL wi = pack2(w.x, w.x), wf = pack2(w.y, w.y);
                ULL wg = pack2(w.z, w.z), wo = pack2(w.w, w.w);
                const ulonglong2* hp = (const ulonglong2*)(hb + (size_t)k * (HP * 4));
                ulonglong2 a0 = hp[0], a1 = hp[1];
                #pragma unroll
                for (int p = 0; p < 4; p++) {
                    ULL hv = (p == 0) ? a0.x : (p == 1) ? a0.y : (p == 2) ? a1.x : a1.y;
                    acc[0][p] = fma2(hv, wi, acc[0][p]);
                    acc[1][p] = fma2(hv, wf, acc[1][p]);
                    acc[2][p] = fma2(hv, wg, acc[2][p]);
                    acc[3][p] = fma2(hv, wo, acc[3][p]);
                }
                ulonglong2 a2 = hp[2], a3 = hp[3];
                #pragma unroll
                for (int p = 4; p < 8; p++) {
                    ULL hv = (p == 4) ? a2.x : (p == 5) ? a2.y : (p == 6) ? a3.x : a3.y;
                    acc[0][p] = fma2(hv, wi, acc[0][p]);
                    acc[1][p] = fma2(hv, wf, acc[1][p]);
                    acc[2][p] = fma2(hv, wg, acc[2][p]);
                    acc[3][p] = fma2(hv, wo, acc[3][p]);
                }
                w = wn;
            }
        }
        __syncthreads();                                     // (1) GEMV1 reads done
        #pragma unroll
        for (int p = 0; p < 8; p++) {
            float2 iv = unpack2(acc[0][p]);
            float2 fv = unpack2(acc[1][p]);
            float2 gv = unpack2(acc[2][p]);
            float2 ov = unpack2(acc[3][p]);
            int rr = r0 + 2 * p;
            float c0 = c1s[u * CP + rr], c1 = c1s[u * CP + rr + 1];
            c0 = sigf(fv.x) * c0 + sigf(iv.x) * tanhe(gv.x);
            c1 = sigf(fv.y) * c1 + sigf(iv.y) * tanhe(gv.y);
            c1s[u * CP + rr]     = c0;
            c1s[u * CP + rr + 1] = c1;
            *(float2*)(h1s + u * HP + rr) =
                make_float2(sigf(ov.x) * tanhe(c0), sigf(ov.y) * tanhe(c1));
        }
        __syncthreads();                                     // (2) h1_new visible

        // ======== layer 2: acc = b2 + h1_new @ W2 + h2 @ U2 ========
        #pragma unroll
        for (int p = 0; p < 8; p++) {
            acc[0][p] = b2i; acc[1][p] = b2f; acc[2][p] = b2g; acc[3][p] = b2o;
        }
        {
            float4 w = g_w2q[u], v = g_u2q[u];
            const char* hb1 = (const char*)(h1s + r0);
            const char* hb2 = (const char*)(h2s + r0);
            #pragma unroll 2
            for (int k = 0; k < 256; k++) {
                float4 wn = g_w2q[(k + 1) * 256 + u];
                float4 vn = g_u2q[(k + 1) * 256 + u];
                ULL wi = pack2(w.x, w.x), wf = pack2(w.y, w.y);
                ULL wg = pack2(w.z, w.z), wo = pack2(w.w, w.w);
                ULL vi = pack2(v.x, v.x), vf = pack2(v.y, v.y);
                ULL vg = pack2(v.z, v.z), vo = pack2(v.w, v.w);
                const ulonglong2* hp1 = (const ulonglong2*)(hb1 + (size_t)k * (HP * 4));
                const ulonglong2* hp2 = (const ulonglong2*)(hb2 + (size_t)k * (HP * 4));
                {
                    ulonglong2 a0 = hp1[0], a1 = hp1[1];
                    ulonglong2 b0 = hp2[0], b1v = hp2[1];
                    #pragma unroll
                    for (int p = 0; p < 4; p++) {
                        ULL h1v = (p == 0) ? a0.x : (p == 1) ? a0.y : (p == 2) ? a1.x : a1.y;
                        ULL h2v = (p == 0) ? b0.x : (p == 1) ? b0.y : (p == 2) ? b1v.x : b1v.y;
                        acc[0][p] = fma2(h1v, wi, acc[0][p]);
                        acc[1][p] = fma2(h1v, wf, acc[1][p]);
                        acc[2][p] = fma2(h1v, wg, acc[2][p]);
                        acc[3][p] = fma2(h1v, wo, acc[3][p]);
                        acc[0][p] = fma2(h2v, vi, acc[0][p]);
                        acc[1][p] = fma2(h2v, vf, acc[1][p]);
                        acc[2][p] = fma2(h2v, vg, acc[2][p]);
                        acc[3][p] = fma2(h2v, vo, acc[3][p]);
                    }
                }
                {
                    ulonglong2 a2 = hp1[2], a3 = hp1[3];
                    ulonglong2 b2v = hp2[2], b3 = hp2[3];
                    #pragma unroll
                    for (int p = 4; p < 8; p++) {
                        ULL h1v = (p == 4) ? a2.x : (p == 5) ? a2.y : (p == 6) ? a3.x : a3.y;
                        ULL h2v = (p == 4) ? b2v.x : (p == 5) ? b2v.y : (p == 6) ? b3.x : b3.y;
                        acc[0][p] = fma2(h1v, wi, acc[0][p]);
                        acc[1][p] = fma2(h1v, wf, acc[1][p]);
                        acc[2][p] = fma2(h1v, wg, acc[2][p]);
                        acc[3][p] = fma2(h1v, wo, acc[3][p]);
                        acc[0][p] = fma2(h2v, vi, acc[0][p]);
                        acc[1][p] = fma2(h2v, vf, acc[1][p]);
                        acc[2][p] = fma2(h2v, vg, acc[2][p]);
                        acc[3][p] = fma2(h2v, vo, acc[3][p]);
                    }
                }
                w = wn; v = vn;
            }
        }
        __syncthreads();                                     // (3) GEMV2 + proj reads done
        #pragma unroll
        for (int p = 0; p < 8; p++) {
            float2 iv = unpack2(acc[0][p]);
            float2 fv = unpack2(acc[1][p]);
            float2 gv = unpack2(acc[2][p]);
            float2 ov = unpack2(acc[3][p]);
            int rr = r0 + 2 * p;
            float c0 = c2s[u * CP + rr], c1 = c2s[u * CP + rr + 1];
            c0 = sigf(fv.x) * c0 + sigf(iv.x) * tanhe(gv.x);
            c1 = sigf(fv.y) * c1 + sigf(iv.y) * tanhe(gv.y);
            c2s[u * CP + rr]     = c0;
            c2s[u * CP + rr + 1] = c1;
            float2 hn = make_float2(sigf(ov.x) * tanhe(c0), sigf(ov.y) * tanhe(c1));
            *(float2*)(h2s + u * HP + rr) = hn;
            out[((size_t)(rb + rr) * T_STEPS + t) * 256 + u]     = hn.x;
            out[((size_t)(rb + rr + 1) * T_STEPS + t) * 256 + u] = hn.y;
        }
        __syncthreads();                                     // (4) h2_new visible

        // ---- fused mu/logvar projection + sampler (320 threads, 8 rows each) ----
        if (pact) {
            ULL amu[4], alv[4];
            #pragma unroll
            for (int q = 0; q < 4; q++) { amu[q] = 0ULL; alv[q] = 0ULL; }
            const char* hb = (const char*)(h2s + pr0);
            float2 wv = g_pw2[pf];
            #pragma unroll 2
            for (int k = 0; k < 256; k++) {
                float2 wn = g_pw2[(k + 1) * 80 + pf];
                ULL wmu = pack2(wv.x, wv.x), wlv = pack2(wv.y, wv.y);
                const ulonglong2* hp = (const ulonglong2*)(hb + (size_t)k * (HP * 4));
                ulonglong2 h01 = hp[0], h23 = hp[1];
                #pragma unroll
                for (int q = 0; q < 4; q++) {
                    ULL hv = (q == 0) ? h01.x : (q == 1) ? h01.y : (q == 2) ? h23.x : h23.y;
                    amu[q] = fma2(hv, wmu, amu[q]);
                    alv[q] = fma2(hv, wlv, alv[q]);
                }
                wv = wn;
            }
            #pragma unroll
            for (int q = 0; q < 4; q++) {
                float2 mu = unpack2(amu[q]);
                float2 lv = unpack2(alv[q]);
                mu.x += pbmu; mu.y += pbmu;
                lv.x += pblv; lv.y += pblv;
                int r = pr0 + 2 * q;
                size_t b0 = ((size_t)(rb + r)     * T_STEPS + t) * 80 + pf;
                size_t b1 = ((size_t)(rb + r + 1) * T_STEPS + t) * 80 + pf;
                float e0 = eps[b0], e1 = eps[b1];
                out[41943040u + b0] = mu.x;
                out[41943040u + b1] = mu.y;
                out[55050240u + b0] = lv.x;
                out[55050240u + b1] = lv.y;
                out[68157440u + b0] = e0 * __expf(0.5f * mu.x) + lv.x;
                out[68157440u + b1] = e1 * __expf(0.5f * mu.y) + lv.y;
            }
        }
        // no barrier needed: next-step writes to h1s/h2s are behind barriers (1)/(3)
    }
}

extern "C" void kernel_launch(void* const* d_in, const int* in_sizes, int n_in,
                              void* d_out, int out_size) {
    // order: x, z1, z2, eps, W1, U1, b1, W2, U2, b2, Wmu, bmu, Wlv, blv
    const float* z1  = (const float*)d_in[1];
    const float* z2  = (const float*)d_in[2];
    const float* eps = (const float*)d_in[3];
    const float* W1  = (const float*)d_in[4];
    const float* U1  = (const float*)d_in[5];
    const float* b1  = (const float*)d_in[6];
    const float* W2  = (const float*)d_in[7];
    const float* U2  = (const float*)d_in[8];
    const float* b2  = (const float*)d_in[9];
    const float* Wmu = (const float*)d_in[10];
    const float* bmu = (const float*)d_in[11];
    const float* Wlv = (const float*)d_in[12];
    const float* blv = (const float*)d_in[13];
    float* out = (float*)d_out;

    cudaFuncSetAttribute(lstm_kernel, cudaFuncAttributeMaxDynamicSharedMemorySize, SMEM_BYTES);

    repack_kernel<<<256, 256>>>(W1, U1, W2, U2, Wmu, Wlv);
    xw1_kernel<<<1024, 256>>>(z1, z2, b1);
    lstm_kernel<<<256, 512, SMEM_BYTES>>>(b2, bmu, blv, eps, out);
}